// round 7
// baseline (speedup 1.0000x reference)
#include <cuda_runtime.h>
#include <cuda_fp16.h>
#include <cstdint>

#define QS    2048.0f
#define IQS   (1.0f/2048.0f)
#define NEGQ  (-20000)

// Problem constants
#define B    8
#define CIN  64
#define COUT 64
#define H    64
#define W    64
#define HW   (H*W)

// Padded quantized x: [B][CIN][66][72] s16 (halo + width pad)
#define XPH  66
#define XPW  72
#define XPWW (XPW/2)      // 36 uint32 words per row
#define XPC  (XPH*XPWW)   // 2376 words per cin-plane

// Dup weights (s16 pair): [CIN][COUT][12] words
#define WPC  12

// Tiling
#define TW   32
#define TH   4
#define COB  16
#define COT  4
#define NC   4
#define XROW 18
#define XS_C (6*XROW)              // 108 words per cin
#define NXSW (NC*XS_C)             // 432
#define WS_C (COB*WPC)             // 192
#define NWSW (NC*WS_C)             // 768
#define NITER (CIN/NC)             // 16

__device__ unsigned xq_g[(size_t)B*CIN*XPC];
__device__ unsigned wq_g[CIN*COUT*WPC];

#define CP_ASYNC4(dst, src) \
    asm volatile("cp.async.ca.shared.global [%0], [%1], 4;\n" :: "r"(dst), "l"(src))
#define CP_COMMIT() asm volatile("cp.async.commit_group;\n" ::: "memory")
#define CP_WAIT0()  asm volatile("cp.async.wait_group 0;\n" ::: "memory")

__device__ __forceinline__ unsigned pack16(int lo, int hi) {
    return (unsigned)(lo & 0xFFFF) | ((unsigned)hi << 16);
}

// ---- prep 1: pad + quantize x (grid-stride x4 for MLP) ----
__global__ void prep_x(const float* __restrict__ x)
{
    const int total  = B * CIN * XPC;
    const int stride = gridDim.x * blockDim.x;
    int idx = blockIdx.x * blockDim.x + threadIdx.x;
#pragma unroll 4
    for (int k = 0; k < 4; ++k, idx += stride) {
        if (idx >= total) break;
        int ww2 = idx % XPWW;
        int t   = idx / XPWW;
        int hh  = t % XPH;
        int bc  = t / XPH;
        int q0 = NEGQ, q1 = NEGQ;
        int c0 = ww2 * 2, c1 = c0 + 1;
        if (hh >= 1 && hh <= H) {
            const float* row = x + (size_t)bc * HW + (hh - 1) * W;
            if (c0 >= 1 && c0 <= W) q0 = __float2int_rn(row[c0 - 1] * QS);
            if (c1 >= 1 && c1 <= W) q1 = __float2int_rn(row[c1 - 1] * QS);
        }
        xq_g[idx] = pack16(q0, q1);
    }
}

// ---- prep 2: quantize + duplicate weights ----
__global__ void prep_w(const float* __restrict__ wgt)
{
    int idx = blockIdx.x * blockDim.x + threadIdx.x;
    if (idx >= CIN * COUT * WPC) return;
    int t  = idx % WPC;
    int q  = idx / WPC;
    int co = q % COUT;
    int ci = q / COUT;
    int v = (t < 9) ? __float2int_rn(wgt[(co * CIN + ci) * 9 + t] * QS) : 0;
    wq_g[idx] = pack16(v, v);
}

__global__ __launch_bounds__(128, 7)
void maxconv2d_kernel(float* __restrict__ out)
{
    __shared__ __align__(16) unsigned xs[2][NXSW];
    __shared__ __align__(16) unsigned ws[2][NWSW];

    const int tid  = threadIdx.x;
    const int b    = blockIdx.z >> 2;
    const int co0  = (blockIdx.z & 3) * COB;
    const int h0   = blockIdx.y * TH;
    const int w0   = blockIdx.x * TW;

    const int cog  = tid >> 5;
    const int lane = tid & 31;
    const int r    = lane >> 3;
    const int cg   = (lane & 7) << 2;

    const unsigned NEG2 = pack16(NEGQ, NEGQ);
    unsigned A[COT][2];
#pragma unroll
    for (int u = 0; u < COT; ++u) { A[u][0] = NEG2; A[u][1] = NEG2; }

    // ---- x staging slots: 432 words, 4 slots (last partial tid<48) ----
    int xgo[4];
#pragma unroll
    for (int k = 0; k < 4; ++k) {
        int i  = tid + 128 * k;
        int c  = i / XS_C;
        int rm = i - c * XS_C;
        int rr = rm / XROW;
        int wc = rm - rr * XROW;
        xgo[k] = c * XPC + (h0 + rr) * XPWW + (w0 >> 1) + wc;
    }
    // ---- w staging slots: 768 words, 6 exact slots ----
    int wgo[6], wso[6];
#pragma unroll
    for (int k = 0; k < 6; ++k) {
        int i  = tid + 128 * k;
        int c  = i / WS_C;
        int rm = i - c * WS_C;
        int co = rm / WPC;
        int t  = rm - co * WPC;
        wso[k] = c * WS_C + co * WPC + t;
        wgo[k] = (c * COUT + co0 + co) * WPC + t;
    }

    const unsigned* xb = xq_g + (size_t)b * CIN * XPC;
    const unsigned* wb = wq_g;

    const uint32_t xs_s = (uint32_t)__cvta_generic_to_shared(&xs[0][0]);
    const uint32_t ws_s = (uint32_t)__cvta_generic_to_shared(&ws[0][0]);

    // ---- stage 0 ----
    {
#pragma unroll
        for (int k = 0; k < 4; ++k)
            if (k < 3 || tid < NXSW - 384)
                CP_ASYNC4(xs_s + (uint32_t)(tid + 128 * k) * 4u, xb + xgo[k]);
#pragma unroll
        for (int k = 0; k < 6; ++k)
            CP_ASYNC4(ws_s + (uint32_t)wso[k] * 4u, wb + wgo[k]);
        CP_COMMIT();
    }

    int buf = 0;
    for (int it = 0; it < NITER; ++it) {
        CP_WAIT0();
        __syncthreads();

        if (it + 1 < NITER) {
            const unsigned* xc = xb + (size_t)(it + 1) * NC * XPC;
            const unsigned* wc = wb + (size_t)(it + 1) * NC * COUT * WPC;
            const uint32_t xd = xs_s + (uint32_t)((buf ^ 1) * NXSW) * 4u;
            const uint32_t wd = ws_s + (uint32_t)((buf ^ 1) * NWSW) * 4u;
#pragma unroll
            for (int k = 0; k < 4; ++k)
                if (k < 3 || tid < NXSW - 384)
                    CP_ASYNC4(xd + (uint32_t)(tid + 128 * k) * 4u, xc + xgo[k]);
#pragma unroll
            for (int k = 0; k < 6; ++k)
                CP_ASYNC4(wd + (uint32_t)wso[k] * 4u, wc + wgo[k]);
            CP_COMMIT();
        }

        // ---- compute: DPX max(a+b, c) on s16x2 ----
        const unsigned* xsb = xs[buf];
        const unsigned* wsb = ws[buf];
#pragma unroll
        for (int c = 0; c < NC; ++c) {
            unsigned xw[3][5];
#pragma unroll
            for (int dr = 0; dr < 3; ++dr) {
                int wi = c * XS_C + (r + dr) * XROW + (cg >> 1);
                uint2    h01 = *reinterpret_cast<const uint2*>(xsb + wi);
                unsigned h2  = xsb[wi + 2];
                xw[dr][0] = h01.x;
                xw[dr][1] = __byte_perm(h01.x, h01.y, 0x5432);
                xw[dr][2] = h01.y;
                xw[dr][3] = __byte_perm(h01.y, h2, 0x5432);
                xw[dr][4] = h2;
            }
            const unsigned* wrow = wsb + c * WS_C + (cog * COT) * WPC;
#pragma unroll
            for (int u = 0; u < COT; ++u) {
                uint4 q0 = *reinterpret_cast<const uint4*>(wrow + u * WPC);
                uint4 q1 = *reinterpret_cast<const uint4*>(wrow + u * WPC + 4);
                unsigned t8 = wrow[u * WPC + 8];
                unsigned tw[9] = { q0.x, q0.y, q0.z, q0.w, q1.x, q1.y, q1.z, q1.w, t8 };
#pragma unroll
                for (int dr = 0; dr < 3; ++dr)
#pragma unroll
                    for (int dc = 0; dc < 3; ++dc) {
                        unsigned t = tw[dr * 3 + dc];
                        A[u][0] = __viaddmax_s16x2(xw[dr][dc],     t, A[u][0]);
                        A[u][1] = __viaddmax_s16x2(xw[dr][dc + 2], t, A[u][1]);
                    }
            }
        }
        buf ^= 1;
    }

    // ---- epilogue: unpack s16 -> float, dequant, float4 store ----
#pragma unroll
    for (int u = 0; u < COT; ++u) {
        const int co = co0 + cog * COT + u;
        float* op = out + (((size_t)b * COUT + co) * H + (h0 + r)) * W + w0 + cg;
        int a0 = (int)(A[u][0] << 16) >> 16;
        int a1 = (int)A[u][0] >> 16;
        int a2 = (int)(A[u][1] << 16) >> 16;
        int a3 = (int)A[u][1] >> 16;
        *reinterpret_cast<float4*>(op) =
            make_float4(a0 * IQS, a1 * IQS, a2 * IQS, a3 * IQS);
    }
}

extern "C" void kernel_launch(void* const* d_in, const int* in_sizes, int n_in,
                              void* d_out, int out_size)
{
    const float* x   = (const float*)d_in[0];
    const float* wgt = (const float*)d_in[1];
    float* out       = (float*)d_out;

    const int nx = B * CIN * XPC;
    prep_x<<<(nx + 1023) / 1024, 256>>>(x);     // 4-deep grid-stride
    const int nw = CIN * COUT * WPC;
    prep_w<<<(nw + 255) / 256, 256>>>(wgt);

    dim3 grid(W / TW, H / TH, B * (COUT / COB));  // 1024 blocks
    maxconv2d_kernel<<<grid, 128>>>(out);
}

// round 8
// speedup vs baseline: 1.0391x; 1.0391x over previous
#include <cuda_runtime.h>
#include <cstdint>

#define QS    2048.0f
#define IQS   (1.0f/2048.0f)
#define NEGQ  (-20000)

// Problem constants
#define B    8
#define CIN  64
#define COUT 64
#define H    64
#define W    64
#define HW   (H*W)

// Padded quantized x: [B][CIN][66][36 words] s16x2
#define XPH  66
#define XPWW 36
#define XPC  (XPH*XPWW)   // 2376 words per cin-plane

// Dup weights: [CIN][COUT][12] words (s16 pair per tap, 9 taps + 3 pad)
#define WPC  12
#define WCIN (COUT*WPC)   // 768 words per cin

// Tiling
#define TW   32
#define TH   4
#define COB  16
#define COT  4
#define NC   8
#define XROW 18
#define XS_C (6*XROW)              // 108 words per cin
#define NXSW (NC*XS_C)             // 864
#define WS_C (COB*WPC)             // 192 words per cin
#define NWSW (NC*WS_C)             // 1536
#define NITER (CIN/NC)             // 8

__device__ __align__(16) unsigned xq_g[(size_t)B*CIN*XPC];
__device__ __align__(16) unsigned wq_g[CIN*COUT*WPC];

#define CP_ASYNC4(dst, src) \
    asm volatile("cp.async.ca.shared.global [%0], [%1], 4;\n" :: "r"(dst), "l"(src))
#define CP_COMMIT() asm volatile("cp.async.commit_group;\n" ::: "memory")
#define CP_WAIT0()  asm volatile("cp.async.wait_group 0;\n" ::: "memory")

__device__ __forceinline__ unsigned pack16(int lo, int hi) {
    return (unsigned)(lo & 0xFFFF) | ((unsigned)hi << 16);
}

// ---- fused prep: x quads (MLP-8) + weights (tail blocks) ----
#define XQB 1188   // = B*CIN*XPC/4/256 exactly
#define WQB 192    // = CIN*COUT*WPC/256 exactly

__global__ void prep_all(const float* __restrict__ x, const float* __restrict__ wgt)
{
    if (blockIdx.x < XQB) {
        int q   = blockIdx.x * blockDim.x + threadIdx.x;  // quad index (4 words, 8 px)
        int t   = q / 9;
        int sg  = q - t * 9;          // quad-in-row (rows have exactly 9 quads)
        int hh  = t % XPH;
        int bc  = t / XPH;
        int xc0 = sg * 8 - 1;         // first x col needed
        const bool rowok = (hh >= 1 && hh <= H);
        const float* row = x + (size_t)bc * HW + (hh - 1) * W;
        int v[8];
#pragma unroll
        for (int e = 0; e < 8; ++e) {
            int xc = xc0 + e;
            float f = (rowok && (unsigned)xc < (unsigned)W) ? row[xc] : 0.0f;
            bool ok = rowok && ((unsigned)xc < (unsigned)W);
            v[e] = ok ? __float2int_rn(f * QS) : NEGQ;
        }
        uint4 st;
        st.x = pack16(v[0], v[1]);
        st.y = pack16(v[2], v[3]);
        st.z = pack16(v[4], v[5]);
        st.w = pack16(v[6], v[7]);
        *reinterpret_cast<uint4*>(&xq_g[(size_t)q * 4]) = st;
    } else {
        int idx = (blockIdx.x - XQB) * blockDim.x + threadIdx.x;
        int tp  = idx % WPC;
        int qd  = idx / WPC;
        int co  = qd % COUT;
        int ci  = qd / COUT;
        int val = (tp < 9) ? __float2int_rn(wgt[(co * CIN + ci) * 9 + tp] * QS) : 0;
        wq_g[idx] = pack16(val, val);
    }
}

__global__ __launch_bounds__(128, 8)
void maxconv2d_kernel(float* __restrict__ out)
{
    __shared__ __align__(16) unsigned xs[2][NXSW];   // 2 x 3456 B
    __shared__ __align__(16) unsigned ws[2][NWSW];   // 2 x 6144 B

    const int tid  = threadIdx.x;
    const int b    = blockIdx.z >> 2;
    const int co0  = (blockIdx.z & 3) * COB;
    const int h0   = blockIdx.y * TH;
    const int w0   = blockIdx.x * TW;

    const int cog  = tid >> 5;
    const int lane = tid & 31;
    const int r    = lane >> 3;
    const int cg   = (lane & 7) << 2;

    const unsigned NEG2 = pack16(NEGQ, NEGQ);
    unsigned A[COT][2];
#pragma unroll
    for (int u = 0; u < COT; ++u) { A[u][0] = NEG2; A[u][1] = NEG2; }

    // ---- affine staging bases ----
    const bool xvalid = (tid < XS_C);                       // 108 stagers
    const int  xsrc0  = (h0 + tid / XROW) * XPWW + (w0 >> 1) + (tid % XROW);
    const bool w2ok   = (tid < WS_C - 128);                 // 64 stagers for 2nd half

    const unsigned* xb = xq_g + (size_t)b * CIN * XPC;      // + cin*XPC + xsrc0
    const unsigned* wb = wq_g + co0 * WPC;                  // + cin*WCIN + m

    const uint32_t xs_s = (uint32_t)__cvta_generic_to_shared(&xs[0][0]);
    const uint32_t ws_s = (uint32_t)__cvta_generic_to_shared(&ws[0][0]);

    // ---- stage 0 (cin 0..7) into buffer 0 ----
    {
#pragma unroll
        for (int k = 0; k < NC; ++k) {
            if (xvalid)
                CP_ASYNC4(xs_s + (uint32_t)(k * XS_C + tid) * 4u, xb + k * XPC + xsrc0);
            CP_ASYNC4(ws_s + (uint32_t)(k * WS_C + tid) * 4u, wb + k * WCIN + tid);
            if (w2ok)
                CP_ASYNC4(ws_s + (uint32_t)(k * WS_C + 128 + tid) * 4u,
                          wb + k * WCIN + 128 + tid);
        }
        CP_COMMIT();
    }

    int buf = 0;
    for (int it = 0; it < NITER; ++it) {
        CP_WAIT0();
        __syncthreads();

        if (it + 1 < NITER) {
            const unsigned* xc = xb + (it + 1) * NC * XPC;
            const unsigned* wc = wb + (it + 1) * NC * WCIN;
            const uint32_t xd = xs_s + (uint32_t)((buf ^ 1) * NXSW) * 4u;
            const uint32_t wd = ws_s + (uint32_t)((buf ^ 1) * NWSW) * 4u;
#pragma unroll
            for (int k = 0; k < NC; ++k) {
                if (xvalid)
                    CP_ASYNC4(xd + (uint32_t)(k * XS_C + tid) * 4u, xc + k * XPC + xsrc0);
                CP_ASYNC4(wd + (uint32_t)(k * WS_C + tid) * 4u, wc + k * WCIN + tid);
                if (w2ok)
                    CP_ASYNC4(wd + (uint32_t)(k * WS_C + 128 + tid) * 4u,
                              wc + k * WCIN + 128 + tid);
            }
            CP_COMMIT();
        }

        // ---- compute: DPX max(a+b, c) on s16x2 ----
        const unsigned* xsb = xs[buf];
        const unsigned* wsb = ws[buf];
#pragma unroll
        for (int c = 0; c < NC; ++c) {
            unsigned xw[3][5];
#pragma unroll
            for (int dr = 0; dr < 3; ++dr) {
                int wi = c * XS_C + (r + dr) * XROW + (cg >> 1);
                uint2    h01 = *reinterpret_cast<const uint2*>(xsb + wi);
                unsigned h2  = xsb[wi + 2];
                xw[dr][0] = h01.x;
                xw[dr][1] = __byte_perm(h01.x, h01.y, 0x5432);
                xw[dr][2] = h01.y;
                xw[dr][3] = __byte_perm(h01.y, h2, 0x5432);
                xw[dr][4] = h2;
            }
            const unsigned* wrow = wsb + c * WS_C + (cog * COT) * WPC;
#pragma unroll
            for (int u = 0; u < COT; ++u) {
                uint4 q0 = *reinterpret_cast<const uint4*>(wrow + u * WPC);
                uint4 q1 = *reinterpret_cast<const uint4*>(wrow + u * WPC + 4);
                unsigned t8 = wrow[u * WPC + 8];
                unsigned tw[9] = { q0.x, q0.y, q0.z, q0.w, q1.x, q1.y, q1.z, q1.w, t8 };
#pragma unroll
                for (int dr = 0; dr < 3; ++dr)
#pragma unroll
                    for (int dc = 0; dc < 3; ++dc) {
                        unsigned t = tw[dr * 3 + dc];
                        A[u][0] = __viaddmax_s16x2(xw[dr][dc],     t, A[u][0]);
                        A[u][1] = __viaddmax_s16x2(xw[dr][dc + 2], t, A[u][1]);
                    }
            }
        }
        buf ^= 1;
    }

    // ---- epilogue: unpack s16 -> float, dequant, float4 store ----
#pragma unroll
    for (int u = 0; u < COT; ++u) {
        const int co = co0 + cog * COT + u;
        float* op = out + (((size_t)b * COUT + co) * H + (h0 + r)) * W + w0 + cg;
        int a0 = (int)(A[u][0] << 16) >> 16;
        int a1 = (int)A[u][0] >> 16;
        int a2 = (int)(A[u][1] << 16) >> 16;
        int a3 = (int)A[u][1] >> 16;
        *reinterpret_cast<float4*>(op) =
            make_float4(a0 * IQS, a1 * IQS, a2 * IQS, a3 * IQS);
    }
}

extern "C" void kernel_launch(void* const* d_in, const int* in_sizes, int n_in,
                              void* d_out, int out_size)
{
    const float* x   = (const float*)d_in[0];
    const float* wgt = (const float*)d_in[1];
    float* out       = (float*)d_out;

    prep_all<<<XQB + WQB, 256>>>(x, wgt);

    dim3 grid(W / TW, H / TH, B * (COUT / COB));  // 1024 blocks
    maxconv2d_kernel<<<grid, 128>>>(out);
}

// round 9
// speedup vs baseline: 1.1473x; 1.1041x over previous
#include <cuda_runtime.h>
#include <cstdint>

#define QS    2048.0f
#define IQS   (1.0f/2048.0f)
#define NEGQ  (-20000)

// Problem constants
#define B    8
#define CIN  64
#define COUT 64
#define H    64
#define W    64
#define HW   (H*W)

// Padded quantized x: [B][CIN][66 rows][36 words] s16x2 (px p <-> col p-1)
#define XPH  66
#define XPWW 36
#define XPC  (XPH*XPWW)   // 2376 words per cin-plane

// Dup weights: [CIN][COUT][12] words (9 taps s16-pair + 3 pad)
#define WPC  12
#define WCIN (COUT*WPC)   // 768

// Tiling: block = 2 rows x 64 px x 16 co, 64 threads (thread = 4 co x 8 px)
#define TH   2
#define COB  16
#define COT  4
#define NC   8
#define XROWW 36                    // staged row stride (words) == source stride
#define XS_C (4*XROWW)              // 144 words per cin (4 staged rows)
#define NXSW (NC*XS_C)              // 1152
#define WS_C (COB*WPC)              // 192
#define NWSW (NC*WS_C)              // 1536
#define NITER (CIN/NC)              // 8

__device__ __align__(16) unsigned xq_g[(size_t)B*CIN*XPC];
__device__ __align__(16) unsigned wq_g[CIN*COUT*WPC];

#define CP_ASYNC16(dst, src) \
    asm volatile("cp.async.cg.shared.global [%0], [%1], 16;\n" :: "r"(dst), "l"(src))
#define CP_COMMIT() asm volatile("cp.async.commit_group;\n" ::: "memory")
#define CP_WAIT0()  asm volatile("cp.async.wait_group 0;\n" ::: "memory")

__device__ __forceinline__ unsigned pack16(int lo, int hi) {
    return (unsigned)(lo & 0xFFFF) | ((unsigned)hi << 16);
}

// ---- fused prep: x quads + weights ----
#define XQB 1188   // = B*CIN*XPC/4/256
#define WQB 192    // = CIN*COUT*WPC/256

__global__ void prep_all(const float* __restrict__ x, const float* __restrict__ wgt)
{
    if (blockIdx.x < XQB) {
        int q   = blockIdx.x * blockDim.x + threadIdx.x;  // quad (4 words = 8 px)
        int t   = q / 9;
        int sg  = q - t * 9;
        int hh  = t % XPH;
        int bc  = t / XPH;
        int xc0 = sg * 8 - 1;
        const bool rowok = (hh >= 1 && hh <= H);
        const float* row = x + (size_t)bc * HW + (hh - 1) * W;
        int v[8];
#pragma unroll
        for (int e = 0; e < 8; ++e) {
            int xc = xc0 + e;
            bool ok = rowok && ((unsigned)xc < (unsigned)W);
            float f = ok ? row[xc] : 0.0f;
            v[e] = ok ? __float2int_rn(f * QS) : NEGQ;
        }
        uint4 st;
        st.x = pack16(v[0], v[1]);
        st.y = pack16(v[2], v[3]);
        st.z = pack16(v[4], v[5]);
        st.w = pack16(v[6], v[7]);
        *reinterpret_cast<uint4*>(&xq_g[(size_t)q * 4]) = st;
    } else {
        int idx = (blockIdx.x - XQB) * blockDim.x + threadIdx.x;
        int tp  = idx % WPC;
        int qd  = idx / WPC;
        int co  = qd % COUT;
        int ci  = qd / COUT;
        int val = (tp < 9) ? __float2int_rn(wgt[(co * CIN + ci) * 9 + tp] * QS) : 0;
        wq_g[idx] = pack16(val, val);
    }
}

__global__ __launch_bounds__(64, 8)
void maxconv2d_kernel(float* __restrict__ out)
{
    __shared__ __align__(16) unsigned xs[2][NXSW];   // 2 x 4608 B
    __shared__ __align__(16) unsigned ws[2][NWSW];   // 2 x 6144 B

    const int tid = threadIdx.x;
    const int b   = blockIdx.z >> 2;
    const int co0 = (blockIdx.z & 3) * COB;
    const int h0  = blockIdx.y * TH;

    const int cog = tid >> 4;          // 0..3 : co group (COT each)
    const int sp  = tid & 15;
    const int r   = sp >> 3;           // 0..1 : row in tile
    const int j   = sp & 7;            // 0..7 : 8-px column group

    // staging identity: 8 stagers per cin, thread stages cin-local cl
    const int s  = tid & 7;
    const int cl = tid >> 3;

    const unsigned NEG2 = pack16(NEGQ, NEGQ);
    unsigned A[COT][4];
#pragma unroll
    for (int u = 0; u < COT; ++u)
#pragma unroll
        for (int p = 0; p < 4; ++p) A[u][p] = NEG2;

    // affine staging offsets (words)
    const int xoff = cl * XPC + h0 * XPWW + 4 * s;     // + 32*m, m=0..4 (m=4: s<4)
    const int woff = cl * WCIN + co0 * WPC + 4 * s;    // + 32*m, m=0..5
    const int xdst = cl * XS_C + 4 * s;
    const int wdst = cl * WS_C + 4 * s;

    const unsigned* xb = xq_g + (size_t)b * CIN * XPC;
    const unsigned* wb = wq_g;

    const uint32_t xs_s = (uint32_t)__cvta_generic_to_shared(&xs[0][0]);
    const uint32_t ws_s = (uint32_t)__cvta_generic_to_shared(&ws[0][0]);

    // ---- stage 0 into buffer 0 ----
    {
#pragma unroll
        for (int m = 0; m < 5; ++m)
            if (m < 4 || s < 4)
                CP_ASYNC16(xs_s + (uint32_t)(xdst + 32 * m) * 4u, xb + xoff + 32 * m);
#pragma unroll
        for (int m = 0; m < 6; ++m)
            CP_ASYNC16(ws_s + (uint32_t)(wdst + 32 * m) * 4u, wb + woff + 32 * m);
        CP_COMMIT();
    }

    int buf = 0;
    for (int it = 0; it < NITER; ++it) {
        CP_WAIT0();
        __syncthreads();

        if (it + 1 < NITER) {
            const unsigned* xc = xb + (it + 1) * NC * XPC;
            const unsigned* wc = wb + (it + 1) * NC * WCIN;
            const uint32_t xd = xs_s + (uint32_t)((buf ^ 1) * NXSW) * 4u;
            const uint32_t wd = ws_s + (uint32_t)((buf ^ 1) * NWSW) * 4u;
#pragma unroll
            for (int m = 0; m < 5; ++m)
                if (m < 4 || s < 4)
                    CP_ASYNC16(xd + (uint32_t)(xdst + 32 * m) * 4u, xc + xoff + 32 * m);
#pragma unroll
            for (int m = 0; m < 6; ++m)
                CP_ASYNC16(wd + (uint32_t)(wdst + 32 * m) * 4u, wc + woff + 32 * m);
            CP_COMMIT();
        }

        // ---- compute ----
        const unsigned* xsb = xs[buf];
        const unsigned* wsb = ws[buf];
#pragma unroll
        for (int c = 0; c < NC; ++c) {
            // weights for this cin: 4 co x 9 taps, resident in registers
            unsigned tw[COT][9];
            const unsigned* wrow = wsb + c * WS_C + cog * (COT * WPC);
#pragma unroll
            for (int u = 0; u < COT; ++u) {
                uint4 q0 = *reinterpret_cast<const uint4*>(wrow + u * WPC);
                uint4 q1 = *reinterpret_cast<const uint4*>(wrow + u * WPC + 4);
                tw[u][0] = q0.x; tw[u][1] = q0.y; tw[u][2] = q0.z; tw[u][3] = q0.w;
                tw[u][4] = q1.x; tw[u][5] = q1.y; tw[u][6] = q1.z; tw[u][7] = q1.w;
                tw[u][8] = wrow[u * WPC + 8];
            }
#pragma unroll
            for (int dr = 0; dr < 3; ++dr) {
                const unsigned* base = xsb + c * XS_C + (r + dr) * XROWW + 4 * j;
                uint4 q = *reinterpret_cast<const uint4*>(base);
                unsigned Wv[5] = { q.x, q.y, q.z, q.w, base[4] };
                unsigned S[4];
#pragma unroll
                for (int i = 0; i < 4; ++i)
                    S[i] = __byte_perm(Wv[i], Wv[i + 1], 0x5432);
#pragma unroll
                for (int u = 0; u < COT; ++u) {
                    const unsigned t0 = tw[u][dr * 3 + 0];
                    const unsigned t1 = tw[u][dr * 3 + 1];
                    const unsigned t2 = tw[u][dr * 3 + 2];
#pragma unroll
                    for (int p = 0; p < 4; ++p) {
                        A[u][p] = __viaddmax_s16x2(Wv[p],     t0, A[u][p]);
                        A[u][p] = __viaddmax_s16x2(S[p],      t1, A[u][p]);
                        A[u][p] = __viaddmax_s16x2(Wv[p + 1], t2, A[u][p]);
                    }
                }
            }
        }
        buf ^= 1;
    }

    // ---- epilogue: dequant, 2x float4 per co ----
#pragma unroll
    for (int u = 0; u < COT; ++u) {
        const int co = co0 + cog * COT + u;
        float* op = out + (((size_t)b * COUT + co) * H + (h0 + r)) * W + j * 8;
        float f[8];
#pragma unroll
        for (int p = 0; p < 4; ++p) {
            f[2 * p]     = ((int)(A[u][p] << 16) >> 16) * IQS;
            f[2 * p + 1] = ((int)A[u][p] >> 16) * IQS;
        }
        *reinterpret_cast<float4*>(op)     = make_float4(f[0], f[1], f[2], f[3]);
        *reinterpret_cast<float4*>(op + 4) = make_float4(f[4], f[5], f[6], f[7]);
    }
}

extern "C" void kernel_launch(void* const* d_in, const int* in_sizes, int n_in,
                              void* d_out, int out_size)
{
    const float* x   = (const float*)d_in[0];
    const float* wgt = (const float*)d_in[1];
    float* out       = (float*)d_out;

    prep_all<<<XQB + WQB, 256>>>(x, wgt);

    dim3 grid(1, H / TH, B * (COUT / COB));   // (1, 32, 32) = 1024 blocks
    maxconv2d_kernel<<<grid, 64>>>(out);
}

// round 10
// speedup vs baseline: 1.1944x; 1.0411x over previous
#include <cuda_runtime.h>
#include <cstdint>

#define QS    2048.0f
#define IQS   (1.0f/2048.0f)
#define NEGQ  (-20000)

// Problem constants
#define B    8
#define CIN  64
#define COUT 64
#define H    64
#define W    64
#define HW   (H*W)

// Padded quantized x: [B][CIN][66 rows][36 words] s16x2
#define XPH  66
#define XPWW 36
#define XPC  (XPH*XPWW)   // 2376 words per cin-plane

// Dup weights: [CIN][COUT][12] words
#define WPC  12
#define WCIN (COUT*WPC)   // 768

// Tiling: block = 2 rows x 64 px x 16 co x 32 cin (half), 64 threads
#define TH   2
#define COB  16
#define COT  4
#define NC   4
#define CHALF 32
#define XROWW 36
#define XS_C (4*XROWW)              // 144 words per cin (4 rows, contiguous in src)
#define NXSW (NC*XS_C)              // 576
#define WS_C (COB*WPC)              // 192
#define NWSW (NC*WS_C)              // 768
#define NITER (CHALF/NC)            // 8

#define NPXW (B*COUT*H*(W/2))       // 1,048,576 packed words per half... (2 px/word)

__device__ __align__(16) unsigned xq_g[(size_t)B*CIN*XPC];
__device__ __align__(16) unsigned wq_g[CIN*COUT*WPC];
__device__ __align__(16) unsigned scr_g[2][NPXW];

#define CP_ASYNC16(dst, src) \
    asm volatile("cp.async.cg.shared.global [%0], [%1], 16;\n" :: "r"(dst), "l"(src))
#define CP_COMMIT() asm volatile("cp.async.commit_group;\n" ::: "memory")
#define CP_WAIT0()  asm volatile("cp.async.wait_group 0;\n" ::: "memory")

__device__ __forceinline__ unsigned pack16(int lo, int hi) {
    return (unsigned)(lo & 0xFFFF) | ((unsigned)hi << 16);
}

// ---- fused prep: x quads + weights ----
#define XQB 1188   // = B*CIN*XPC/4/256
#define WQB 192    // = CIN*COUT*WPC/256

__global__ void prep_all(const float* __restrict__ x, const float* __restrict__ wgt)
{
    if (blockIdx.x < XQB) {
        int q   = blockIdx.x * blockDim.x + threadIdx.x;
        int t   = q / 9;
        int sg  = q - t * 9;
        int hh  = t % XPH;
        int bc  = t / XPH;
        int xc0 = sg * 8 - 1;
        const bool rowok = (hh >= 1 && hh <= H);
        const float* row = x + (size_t)bc * HW + (hh - 1) * W;
        int v[8];
#pragma unroll
        for (int e = 0; e < 8; ++e) {
            int xc = xc0 + e;
            bool ok = rowok && ((unsigned)xc < (unsigned)W);
            float f = ok ? row[xc] : 0.0f;
            v[e] = ok ? __float2int_rn(f * QS) : NEGQ;
        }
        uint4 st;
        st.x = pack16(v[0], v[1]);
        st.y = pack16(v[2], v[3]);
        st.z = pack16(v[4], v[5]);
        st.w = pack16(v[6], v[7]);
        *reinterpret_cast<uint4*>(&xq_g[(size_t)q * 4]) = st;
    } else {
        int idx = (blockIdx.x - XQB) * blockDim.x + threadIdx.x;
        int tp  = idx % WPC;
        int qd  = idx / WPC;
        int co  = qd % COUT;
        int ci  = qd / COUT;
        int val = (tp < 9) ? __float2int_rn(wgt[(co * CIN + ci) * 9 + tp] * QS) : 0;
        wq_g[idx] = pack16(val, val);
    }
}

__global__ __launch_bounds__(64, 14)
void maxconv2d_kernel()
{
    __shared__ __align__(16) unsigned xs[2][NXSW];   // 2 x 2304 B
    __shared__ __align__(16) unsigned ws[2][NWSW];   // 2 x 3072 B

    const int tid  = threadIdx.x;
    const int z    = blockIdx.z;
    const int half = z >> 5;               // 0/1 : cin half
    const int b    = (z >> 2) & 7;
    const int co0  = (z & 3) * COB;
    const int h0   = blockIdx.y * TH;

    const int cog = tid >> 4;
    const int sp  = tid & 15;
    const int r   = sp >> 3;
    const int j   = sp & 7;

    // staging identity: 16 stagers per cin (s), 4 cin slots (cl)
    const int s  = tid & 15;
    const int cl = tid >> 4;

    const unsigned NEG2 = pack16(NEGQ, NEGQ);
    unsigned A[COT][4];
#pragma unroll
    for (int u = 0; u < COT; ++u)
#pragma unroll
        for (int p = 0; p < 4; ++p) A[u][p] = NEG2;

    const unsigned* xb = xq_g + (size_t)b * CIN * XPC + (size_t)half * CHALF * XPC
                       + h0 * XPWW;                       // + cin*XPC, contiguous 144 words
    const unsigned* wb = wq_g + (size_t)half * CHALF * WCIN + co0 * WPC;  // + cin*WCIN

    const uint32_t xs_s = (uint32_t)__cvta_generic_to_shared(&xs[0][0]);
    const uint32_t ws_s = (uint32_t)__cvta_generic_to_shared(&ws[0][0]);

    // x: per cin 36 cp.16 by 16 stagers: m=0,1 full + m=2 for s<4
    // w: per cin 48 cp.16 by 16 stagers: m=0..2 exact
    // ---- stage 0 ----
    {
#pragma unroll
        for (int m = 0; m < 3; ++m)
            if (m < 2 || s < 4)
                CP_ASYNC16(xs_s + (uint32_t)(cl * XS_C + 4 * (s + 16 * m)) * 4u,
                           xb + cl * XPC + 4 * (s + 16 * m));
#pragma unroll
        for (int m = 0; m < 3; ++m)
            CP_ASYNC16(ws_s + (uint32_t)(cl * WS_C + 4 * (s + 16 * m)) * 4u,
                       wb + cl * WCIN + 4 * (s + 16 * m));
        CP_COMMIT();
    }

    int buf = 0;
    for (int it = 0; it < NITER; ++it) {
        CP_WAIT0();
        __syncthreads();

        if (it + 1 < NITER) {
            const unsigned* xc = xb + (it + 1) * NC * XPC;
            const unsigned* wc = wb + (it + 1) * NC * WCIN;
            const uint32_t xd = xs_s + (uint32_t)((buf ^ 1) * NXSW) * 4u;
            const uint32_t wd = ws_s + (uint32_t)((buf ^ 1) * NWSW) * 4u;
#pragma unroll
            for (int m = 0; m < 3; ++m)
                if (m < 2 || s < 4)
                    CP_ASYNC16(xd + (uint32_t)(cl * XS_C + 4 * (s + 16 * m)) * 4u,
                               xc + cl * XPC + 4 * (s + 16 * m));
#pragma unroll
            for (int m = 0; m < 3; ++m)
                CP_ASYNC16(wd + (uint32_t)(cl * WS_C + 4 * (s + 16 * m)) * 4u,
                           wc + cl * WCIN + 4 * (s + 16 * m));
            CP_COMMIT();
        }

        // ---- compute ----
        const unsigned* xsb = xs[buf];
        const unsigned* wsb = ws[buf];
#pragma unroll
        for (int c = 0; c < NC; ++c) {
            unsigned tw[COT][9];
            const unsigned* wrow = wsb + c * WS_C + cog * (COT * WPC);
#pragma unroll
            for (int u = 0; u < COT; ++u) {
                uint4 q0 = *reinterpret_cast<const uint4*>(wrow + u * WPC);
                uint4 q1 = *reinterpret_cast<const uint4*>(wrow + u * WPC + 4);
                tw[u][0] = q0.x; tw[u][1] = q0.y; tw[u][2] = q0.z; tw[u][3] = q0.w;
                tw[u][4] = q1.x; tw[u][5] = q1.y; tw[u][6] = q1.z; tw[u][7] = q1.w;
                tw[u][8] = wrow[u * WPC + 8];
            }
#pragma unroll
            for (int dr = 0; dr < 3; ++dr) {
                const unsigned* base = xsb + c * XS_C + (r + dr) * XROWW + 4 * j;
                uint4 q = *reinterpret_cast<const uint4*>(base);
                unsigned Wv[5] = { q.x, q.y, q.z, q.w, base[4] };
                unsigned S[4];
#pragma unroll
                for (int i = 0; i < 4; ++i)
                    S[i] = __byte_perm(Wv[i], Wv[i + 1], 0x5432);
#pragma unroll
                for (int u = 0; u < COT; ++u) {
                    const unsigned t0 = tw[u][dr * 3 + 0];
                    const unsigned t1 = tw[u][dr * 3 + 1];
                    const unsigned t2 = tw[u][dr * 3 + 2];
#pragma unroll
                    for (int p = 0; p < 4; ++p) {
                        A[u][p] = __viaddmax_s16x2(Wv[p],     t0, A[u][p]);
                        A[u][p] = __viaddmax_s16x2(S[p],      t1, A[u][p]);
                        A[u][p] = __viaddmax_s16x2(Wv[p + 1], t2, A[u][p]);
                    }
                }
            }
        }
        buf ^= 1;
    }

    // ---- epilogue: packed partials to scratch ----
#pragma unroll
    for (int u = 0; u < COT; ++u) {
        const int co = co0 + cog * COT + u;
        unsigned* op = &scr_g[half][(((b * COUT + co) * H) + h0 + r) * (W / 2) + j * 4];
        uint4 st; st.x = A[u][0]; st.y = A[u][1]; st.z = A[u][2]; st.w = A[u][3];
        *reinterpret_cast<uint4*>(op) = st;
    }
}

// ---- combine: max of halves + dequant ----
__global__ void combine_k(float* __restrict__ out)
{
    int i = blockIdx.x * blockDim.x + threadIdx.x;     // uint2 index
    uint2 a = reinterpret_cast<const uint2*>(scr_g[0])[i];
    uint2 c = reinterpret_cast<const uint2*>(scr_g[1])[i];
    unsigned m0 = __vmaxs2(a.x, c.x);
    unsigned m1 = __vmaxs2(a.y, c.y);
    float4 f;
    f.x = ((int)(m0 << 16) >> 16) * IQS;
    f.y = ((int)m0 >> 16) * IQS;
    f.z = ((int)(m1 << 16) >> 16) * IQS;
    f.w = ((int)m1 >> 16) * IQS;
    reinterpret_cast<float4*>(out)[i] = f;
}

extern "C" void kernel_launch(void* const* d_in, const int* in_sizes, int n_in,
                              void* d_out, int out_size)
{
    const float* x   = (const float*)d_in[0];
    const float* wgt = (const float*)d_in[1];
    float* out       = (float*)d_out;

    prep_all<<<XQB + WQB, 256>>>(x, wgt);

    dim3 grid(1, H / TH, 2 * B * (COUT / COB));   // (1, 32, 64) = 2048 blocks
    maxconv2d_kernel<<<grid, 64>>>();

    combine_k<<<(NPXW / 2) / 256, 256>>>(out);    // 2048 blocks
}

// round 11
// speedup vs baseline: 1.2522x; 1.0484x over previous
#include <cuda_runtime.h>
#include <cstdint>

#define QS    2048.0f
#define IQS   (1.0f/2048.0f)
#define NEGQ  (-20000)

// Problem constants
#define B    8
#define CIN  64
#define COUT 64
#define H    64
#define W    64
#define HW   (H*W)

// Padded quantized x: [B][CIN][66 rows][36 words] s16x2
#define XPH  66
#define XPWW 36
#define XPC  (XPH*XPWW)   // 2376

// Dup weights: [CIN][COUT][12] words
#define WPC  12
#define WCIN (COUT*WPC)   // 768

// Tiling: block = 2 rows x 64 px x 16 co, 128 threads = 2 cin-half groups of 64
#define TH   2
#define COB  16
#define COT  4
#define NC   4
#define CHALF 32
#define XROWW 36
#define XS_C (4*XROWW)              // 144 words per cin
#define NXSW (NC*XS_C)              // 576
#define WS_C (COB*WPC)              // 192
#define NWSW (NC*WS_C)              // 768
#define NITER (CHALF/NC)            // 8
#define REDS 20                     // smem reduction stride (conflict-free, 16B-aligned)

__device__ __align__(16) unsigned xq_g[(size_t)B*CIN*XPC];
__device__ __align__(16) unsigned wq_g[CIN*COUT*WPC];

#define CP_ASYNC16(dst, src) \
    asm volatile("cp.async.cg.shared.global [%0], [%1], 16;\n" :: "r"(dst), "l"(src))
#define CP_COMMIT() asm volatile("cp.async.commit_group;\n" ::: "memory")
#define CP_WAIT0()  asm volatile("cp.async.wait_group 0;\n" ::: "memory")

__device__ __forceinline__ unsigned pack16(int lo, int hi) {
    return (unsigned)(lo & 0xFFFF) | ((unsigned)hi << 16);
}

// ---- fused prep: x quads (3x LDG.128) + weights ----
#define XQB 1188   // = B*CIN*XPC/4/256
#define WQB 192    // = CIN*COUT*WPC/256

__global__ void prep_all(const float* __restrict__ x, const float* __restrict__ wgt)
{
    if (blockIdx.x < XQB) {
        int q   = blockIdx.x * blockDim.x + threadIdx.x;  // quad (4 words = 8 px)
        int t   = q / 9;
        int sg  = q - t * 9;
        int hh  = t % XPH;
        int bc  = t / XPH;
        const bool rowok = (hh >= 1 && hh <= H);
        const float* row = x + (size_t)bc * HW + (hh - 1) * W;
        const bool aok = rowok && (sg >= 1);
        const bool mok = rowok && (sg < 8);
        float4 fa = aok ? *reinterpret_cast<const float4*>(row + sg * 8 - 4)
                        : make_float4(0.f, 0.f, 0.f, 0.f);
        float4 fm = mok ? *reinterpret_cast<const float4*>(row + sg * 8)
                        : make_float4(0.f, 0.f, 0.f, 0.f);
        float4 fh = mok ? *reinterpret_cast<const float4*>(row + sg * 8 + 4)
                        : make_float4(0.f, 0.f, 0.f, 0.f);
        int v[8];
        v[0] = aok ? __float2int_rn(fa.w * QS) : NEGQ;
        v[1] = mok ? __float2int_rn(fm.x * QS) : NEGQ;
        v[2] = mok ? __float2int_rn(fm.y * QS) : NEGQ;
        v[3] = mok ? __float2int_rn(fm.z * QS) : NEGQ;
        v[4] = mok ? __float2int_rn(fm.w * QS) : NEGQ;
        v[5] = mok ? __float2int_rn(fh.x * QS) : NEGQ;
        v[6] = mok ? __float2int_rn(fh.y * QS) : NEGQ;
        v[7] = mok ? __float2int_rn(fh.z * QS) : NEGQ;
        uint4 st;
        st.x = pack16(v[0], v[1]);
        st.y = pack16(v[2], v[3]);
        st.z = pack16(v[4], v[5]);
        st.w = pack16(v[6], v[7]);
        *reinterpret_cast<uint4*>(&xq_g[(size_t)q * 4]) = st;
    } else {
        int idx = (blockIdx.x - XQB) * blockDim.x + threadIdx.x;
        int tp  = idx % WPC;
        int qd  = idx / WPC;
        int co  = qd % COUT;
        int ci  = qd / COUT;
        int val = (tp < 9) ? __float2int_rn(wgt[(co * CIN + ci) * 9 + tp] * QS) : 0;
        wq_g[idx] = pack16(val, val);
    }
}

__global__ __launch_bounds__(128, 8)
void maxconv2d_kernel(float* __restrict__ out)
{
    __shared__ __align__(16) unsigned xs[4 * NXSW];   // [half][buf] 9216 B
    __shared__ __align__(16) unsigned ws[4 * NWSW];   // [half][buf] 6144 B
    __shared__ __align__(16) unsigned red[64 * REDS]; // 5120 B

    const int tid  = threadIdx.x;
    const int half = tid >> 6;          // cin half handled by this group
    const int gt   = tid & 63;

    const int b   = blockIdx.z >> 2;
    const int co0 = (blockIdx.z & 3) * COB;
    const int h0  = blockIdx.y * TH;

    const int cog = gt >> 4;
    const int sp  = gt & 15;
    const int r   = sp >> 3;
    const int j   = sp & 7;

    const int s  = gt & 15;             // stager lane within group
    const int cl = gt >> 4;             // cin slot 0..3

    const unsigned NEG2 = pack16(NEGQ, NEGQ);
    unsigned A[COT][4];
#pragma unroll
    for (int u = 0; u < COT; ++u)
#pragma unroll
        for (int p = 0; p < 4; ++p) A[u][p] = NEG2;

    const unsigned* xb = xq_g + (size_t)b * CIN * XPC + (size_t)half * CHALF * XPC
                       + h0 * XPWW;
    const unsigned* wb = wq_g + (size_t)half * CHALF * WCIN + co0 * WPC;

    const uint32_t xs_s = (uint32_t)__cvta_generic_to_shared(&xs[0]);
    const uint32_t ws_s = (uint32_t)__cvta_generic_to_shared(&ws[0]);

    // ---- stage 0 into (half, buf=0) ----
    {
        const uint32_t xd = xs_s + (uint32_t)((half * 2) * NXSW) * 4u;
        const uint32_t wd = ws_s + (uint32_t)((half * 2) * NWSW) * 4u;
#pragma unroll
        for (int m = 0; m < 3; ++m)
            if (m < 2 || s < 4)
                CP_ASYNC16(xd + (uint32_t)(cl * XS_C + 4 * (s + 16 * m)) * 4u,
                           xb + cl * XPC + 4 * (s + 16 * m));
#pragma unroll
        for (int m = 0; m < 3; ++m)
            CP_ASYNC16(wd + (uint32_t)(cl * WS_C + 4 * (s + 16 * m)) * 4u,
                       wb + cl * WCIN + 4 * (s + 16 * m));
        CP_COMMIT();
    }

    int buf = 0;
    for (int it = 0; it < NITER; ++it) {
        CP_WAIT0();
        __syncthreads();

        if (it + 1 < NITER) {
            const unsigned* xc = xb + (it + 1) * NC * XPC;
            const unsigned* wc = wb + (it + 1) * NC * WCIN;
            const uint32_t xd = xs_s + (uint32_t)((half * 2 + (buf ^ 1)) * NXSW) * 4u;
            const uint32_t wd = ws_s + (uint32_t)((half * 2 + (buf ^ 1)) * NWSW) * 4u;
#pragma unroll
            for (int m = 0; m < 3; ++m)
                if (m < 2 || s < 4)
                    CP_ASYNC16(xd + (uint32_t)(cl * XS_C + 4 * (s + 16 * m)) * 4u,
                               xc + cl * XPC + 4 * (s + 16 * m));
#pragma unroll
            for (int m = 0; m < 3; ++m)
                CP_ASYNC16(wd + (uint32_t)(cl * WS_C + 4 * (s + 16 * m)) * 4u,
                           wc + cl * WCIN + 4 * (s + 16 * m));
            CP_COMMIT();
        }

        // ---- compute ----
        const unsigned* xsb = xs + (half * 2 + buf) * NXSW;
        const unsigned* wsb = ws + (half * 2 + buf) * NWSW;
#pragma unroll
        for (int c = 0; c < NC; ++c) {
            unsigned tw[COT][9];
            const unsigned* wrow = wsb + c * WS_C + cog * (COT * WPC);
#pragma unroll
            for (int u = 0; u < COT; ++u) {
                uint4 q0 = *reinterpret_cast<const uint4*>(wrow + u * WPC);
                uint4 q1 = *reinterpret_cast<const uint4*>(wrow + u * WPC + 4);
                tw[u][0] = q0.x; tw[u][1] = q0.y; tw[u][2] = q0.z; tw[u][3] = q0.w;
                tw[u][4] = q1.x; tw[u][5] = q1.y; tw[u][6] = q1.z; tw[u][7] = q1.w;
                tw[u][8] = wrow[u * WPC + 8];
            }
#pragma unroll
            for (int dr = 0; dr < 3; ++dr) {
                const unsigned* base = xsb + c * XS_C + (r + dr) * XROWW + 4 * j;
                uint4 q = *reinterpret_cast<const uint4*>(base);
                unsigned Wv[5] = { q.x, q.y, q.z, q.w, base[4] };
                unsigned S[4];
#pragma unroll
                for (int i = 0; i < 4; ++i)
                    S[i] = __byte_perm(Wv[i], Wv[i + 1], 0x5432);
#pragma unroll
                for (int u = 0; u < COT; ++u) {
                    const unsigned t0 = tw[u][dr * 3 + 0];
                    const unsigned t1 = tw[u][dr * 3 + 1];
                    const unsigned t2 = tw[u][dr * 3 + 2];
#pragma unroll
                    for (int p = 0; p < 4; ++p) {
                        A[u][p] = __viaddmax_s16x2(Wv[p],     t0, A[u][p]);
                        A[u][p] = __viaddmax_s16x2(S[p],      t1, A[u][p]);
                        A[u][p] = __viaddmax_s16x2(Wv[p + 1], t2, A[u][p]);
                    }
                }
            }
        }
        buf ^= 1;
    }

    // ---- in-block combine: group 1 -> smem, group 0 reduces + writes ----
    if (half == 1) {
#pragma unroll
        for (int u = 0; u < COT; ++u) {
            uint4 st; st.x = A[u][0]; st.y = A[u][1]; st.z = A[u][2]; st.w = A[u][3];
            *reinterpret_cast<uint4*>(&red[gt * REDS + u * 4]) = st;
        }
    }
    __syncthreads();
    if (half == 0) {
#pragma unroll
        for (int u = 0; u < COT; ++u) {
            uint4 pr = *reinterpret_cast<const uint4*>(&red[gt * REDS + u * 4]);
            unsigned m0 = __vmaxs2(A[u][0], pr.x);
            unsigned m1 = __vmaxs2(A[u][1], pr.y);
            unsigned m2 = __vmaxs2(A[u][2], pr.z);
            unsigned m3 = __vmaxs2(A[u][3], pr.w);
            const int co = co0 + cog * COT + u;
            float* op = out + (((size_t)b * COUT + co) * H + (h0 + r)) * W + j * 8;
            float f[8];
            f[0] = ((int)(m0 << 16) >> 16) * IQS;  f[1] = ((int)m0 >> 16) * IQS;
            f[2] = ((int)(m1 << 16) >> 16) * IQS;  f[3] = ((int)m1 >> 16) * IQS;
            f[4] = ((int)(m2 << 16) >> 16) * IQS;  f[5] = ((int)m2 >> 16) * IQS;
            f[6] = ((int)(m3 << 16) >> 16) * IQS;  f[7] = ((int)m3 >> 16) * IQS;
            *reinterpret_cast<float4*>(op)     = make_float4(f[0], f[1], f[2], f[3]);
            *reinterpret_cast<float4*>(op + 4) = make_float4(f[4], f[5], f[6], f[7]);
        }
    }
}

extern "C" void kernel_launch(void* const* d_in, const int* in_sizes, int n_in,
                              void* d_out, int out_size)
{
    const float* x   = (const float*)d_in[0];
    const float* wgt = (const float*)d_in[1];
    float* out       = (float*)d_out;

    prep_all<<<XQB + WQB, 256>>>(x, wgt);

    dim3 grid(1, H / TH, B * (COUT / COB));   // (1, 32, 32) = 1024 blocks
    maxconv2d_kernel<<<grid, 128>>>(out);
}

// round 12
// speedup vs baseline: 1.2895x; 1.0298x over previous
#include <cuda_runtime.h>
#include <cstdint>

#define QS    2048.0f
#define IQS   (1.0f/2048.0f)
#define NEGQ  (-20000)

// Problem constants
#define B    8
#define CIN  64
#define COUT 64
#define H    64
#define W    64
#define HW   (H*W)

// Padded quantized x: [B][CIN][66 rows][36 words] s16x2
#define XPH  66
#define XPWW 36
#define XPC  (XPH*XPWW)   // 2376

// Dup weights: [CIN][COUT][12] words
#define WPC  12
#define WCIN (COUT*WPC)   // 768

// Tiling: block = 2 rows x 64 px x 16 co, 128 threads = 2 cin-half groups of 64
#define TH   2
#define COB  16
#define COT  4
#define NC   4
#define CHALF 32
#define XROWW 36
#define XS_C (4*XROWW)              // 144 words per cin
#define NXSW (NC*XS_C)              // 576
#define WS_C (COB*WPC)              // 192
#define NWSW (NC*WS_C)              // 768
#define NITER (CHALF/NC)            // 8
#define REDS 20

__device__ __align__(16) unsigned xq_g[(size_t)B*CIN*XPC];
__device__ __align__(16) unsigned wq_g[CIN*COUT*WPC];

#define CP_ASYNC16(dst, src) \
    asm volatile("cp.async.cg.shared.global [%0], [%1], 16;\n" :: "r"(dst), "l"(src))
#define CP_COMMIT() asm volatile("cp.async.commit_group;\n" ::: "memory")
#define CP_WAIT0()  asm volatile("cp.async.wait_group 0;\n" ::: "memory")

__device__ __forceinline__ unsigned pack16(int lo, int hi) {
    return (unsigned)(lo & 0xFFFF) | ((unsigned)hi << 16);
}

// ---- fused prep: x quads (3x LDG.128) + weights ----
#define XQB 1188
#define WQB 192

__global__ void prep_all(const float* __restrict__ x, const float* __restrict__ wgt)
{
    if (blockIdx.x < XQB) {
        int q   = blockIdx.x * blockDim.x + threadIdx.x;
        int t   = q / 9;
        int sg  = q - t * 9;
        int hh  = t % XPH;
        int bc  = t / XPH;
        const bool rowok = (hh >= 1 && hh <= H);
        const float* row = x + (size_t)bc * HW + (hh - 1) * W;
        const bool aok = rowok && (sg >= 1);
        const bool mok = rowok && (sg < 8);
        float4 fa = aok ? *reinterpret_cast<const float4*>(row + sg * 8 - 4)
                        : make_float4(0.f, 0.f, 0.f, 0.f);
        float4 fm = mok ? *reinterpret_cast<const float4*>(row + sg * 8)
                        : make_float4(0.f, 0.f, 0.f, 0.f);
        float4 fh = mok ? *reinterpret_cast<const float4*>(row + sg * 8 + 4)
                        : make_float4(0.f, 0.f, 0.f, 0.f);
        int v[8];
        v[0] = aok ? __float2int_rn(fa.w * QS) : NEGQ;
        v[1] = mok ? __float2int_rn(fm.x * QS) : NEGQ;
        v[2] = mok ? __float2int_rn(fm.y * QS) : NEGQ;
        v[3] = mok ? __float2int_rn(fm.z * QS) : NEGQ;
        v[4] = mok ? __float2int_rn(fm.w * QS) : NEGQ;
        v[5] = mok ? __float2int_rn(fh.x * QS) : NEGQ;
        v[6] = mok ? __float2int_rn(fh.y * QS) : NEGQ;
        v[7] = mok ? __float2int_rn(fh.z * QS) : NEGQ;
        uint4 st;
        st.x = pack16(v[0], v[1]);
        st.y = pack16(v[2], v[3]);
        st.z = pack16(v[4], v[5]);
        st.w = pack16(v[6], v[7]);
        *reinterpret_cast<uint4*>(&xq_g[(size_t)q * 4]) = st;
    } else {
        int idx = (blockIdx.x - XQB) * blockDim.x + threadIdx.x;
        int tp  = idx % WPC;
        int qd  = idx / WPC;
        int co  = qd % COUT;
        int ci  = qd / COUT;
        int val = (tp < 9) ? __float2int_rn(wgt[(co * CIN + ci) * 9 + tp] * QS) : 0;
        wq_g[idx] = pack16(val, val);
    }
}

__device__ __forceinline__
void compute_chunk(const unsigned* __restrict__ xsb, const unsigned* __restrict__ wsb,
                   int c, int cog, int r, int j, unsigned (&A)[COT][4])
{
    unsigned tw[COT][9];
    const unsigned* wrow = wsb + c * WS_C + cog * (COT * WPC);
#pragma unroll
    for (int u = 0; u < COT; ++u) {
        uint4 q0 = *reinterpret_cast<const uint4*>(wrow + u * WPC);
        uint4 q1 = *reinterpret_cast<const uint4*>(wrow + u * WPC + 4);
        tw[u][0] = q0.x; tw[u][1] = q0.y; tw[u][2] = q0.z; tw[u][3] = q0.w;
        tw[u][4] = q1.x; tw[u][5] = q1.y; tw[u][6] = q1.z; tw[u][7] = q1.w;
        tw[u][8] = wrow[u * WPC + 8];
    }
#pragma unroll
    for (int dr = 0; dr < 3; ++dr) {
        const unsigned* base = xsb + c * XS_C + (r + dr) * XROWW + 4 * j;
        uint4 q = *reinterpret_cast<const uint4*>(base);
        unsigned Wv[5] = { q.x, q.y, q.z, q.w, base[4] };
        unsigned S[4];
#pragma unroll
        for (int i = 0; i < 4; ++i)
            S[i] = __byte_perm(Wv[i], Wv[i + 1], 0x5432);
#pragma unroll
        for (int u = 0; u < COT; ++u) {
            const unsigned t0 = tw[u][dr * 3 + 0];
            const unsigned t1 = tw[u][dr * 3 + 1];
            const unsigned t2 = tw[u][dr * 3 + 2];
#pragma unroll
            for (int p = 0; p < 4; ++p) {
                A[u][p] = __viaddmax_s16x2(Wv[p],     t0, A[u][p]);
                A[u][p] = __viaddmax_s16x2(S[p],      t1, A[u][p]);
                A[u][p] = __viaddmax_s16x2(Wv[p + 1], t2, A[u][p]);
            }
        }
    }
}

__global__ __launch_bounds__(128, 8)
void maxconv2d_kernel(float* __restrict__ out)
{
    __shared__ __align__(16) unsigned xs[4 * NXSW];
    __shared__ __align__(16) unsigned ws[4 * NWSW];
    __shared__ __align__(16) unsigned red[64 * REDS];

    const int tid  = threadIdx.x;
    const int half = tid >> 6;
    const int gt   = tid & 63;

    const int b   = blockIdx.z >> 2;
    const int co0 = (blockIdx.z & 3) * COB;
    const int h0  = blockIdx.y * TH;

    const int cog = gt >> 4;
    const int sp  = gt & 15;
    const int r   = sp >> 3;
    const int j   = sp & 7;

    const int s  = gt & 15;
    const int cl = gt >> 4;

    const unsigned NEG2 = pack16(NEGQ, NEGQ);
    unsigned A[COT][4];
#pragma unroll
    for (int u = 0; u < COT; ++u)
#pragma unroll
        for (int p = 0; p < 4; ++p) A[u][p] = NEG2;

    const unsigned* xb = xq_g + (size_t)b * CIN * XPC + (size_t)half * CHALF * XPC
                       + h0 * XPWW;
    const unsigned* wb = wq_g + (size_t)half * CHALF * WCIN + co0 * WPC;

    const uint32_t xs_s = (uint32_t)__cvta_generic_to_shared(&xs[0]);
    const uint32_t ws_s = (uint32_t)__cvta_generic_to_shared(&ws[0]);

    // ---- stage 0 into (half, buf=0) ----
    {
        const uint32_t xd = xs_s + (uint32_t)((half * 2) * NXSW) * 4u;
        const uint32_t wd = ws_s + (uint32_t)((half * 2) * NWSW) * 4u;
#pragma unroll
        for (int m = 0; m < 3; ++m)
            if (m < 2 || s < 4)
                CP_ASYNC16(xd + (uint32_t)(cl * XS_C + 4 * (s + 16 * m)) * 4u,
                           xb + cl * XPC + 4 * (s + 16 * m));
#pragma unroll
        for (int m = 0; m < 3; ++m)
            CP_ASYNC16(wd + (uint32_t)(cl * WS_C + 4 * (s + 16 * m)) * 4u,
                       wb + cl * WCIN + 4 * (s + 16 * m));
        CP_COMMIT();
    }

    int buf = 0;
    for (int it = 0; it < NITER; ++it) {
        CP_WAIT0();
        __syncthreads();

        const bool more = (it + 1 < NITER);
        const unsigned* xc = xb + (it + 1) * NC * XPC;
        const unsigned* wc = wb + (it + 1) * NC * WCIN;
        const uint32_t xd = xs_s + (uint32_t)((half * 2 + (buf ^ 1)) * NXSW) * 4u;
        const uint32_t wd = ws_s + (uint32_t)((half * 2 + (buf ^ 1)) * NWSW) * 4u;

        const unsigned* xsb = xs + (half * 2 + buf) * NXSW;
        const unsigned* wsb = ws + (half * 2 + buf) * NWSW;

        // chunk 0, then x staging batch (3 cp.async, de-batched)
        compute_chunk(xsb, wsb, 0, cog, r, j, A);
        if (more) {
#pragma unroll
            for (int m = 0; m < 3; ++m)
                if (m < 2 || s < 4)
                    CP_ASYNC16(xd + (uint32_t)(cl * XS_C + 4 * (s + 16 * m)) * 4u,
                               xc + cl * XPC + 4 * (s + 16 * m));
        }
        // chunk 1, then w staging batch + commit
        compute_chunk(xsb, wsb, 1, cog, r, j, A);
        if (more) {
#pragma unroll
            for (int m = 0; m < 3; ++m)
                CP_ASYNC16(wd + (uint32_t)(cl * WS_C + 4 * (s + 16 * m)) * 4u,
                           wc + cl * WCIN + 4 * (s + 16 * m));
            CP_COMMIT();
        }
        compute_chunk(xsb, wsb, 2, cog, r, j, A);
        compute_chunk(xsb, wsb, 3, cog, r, j, A);

        buf ^= 1;
    }

    // ---- in-block combine ----
    if (half == 1) {
#pragma unroll
        for (int u = 0; u < COT; ++u) {
            uint4 st; st.x = A[u][0]; st.y = A[u][1]; st.z = A[u][2]; st.w = A[u][3];
            *reinterpret_cast<uint4*>(&red[gt * REDS + u * 4]) = st;
        }
    }
    __syncthreads();
    if (half == 0) {
#pragma unroll
        for (int u = 0; u < COT; ++u) {
            uint4 pr = *reinterpret_cast<const uint4*>(&red[gt * REDS + u * 4]);
            unsigned m0 = __vmaxs2(A[u][0], pr.x);
            unsigned m1 = __vmaxs2(A[u][1], pr.y);
            unsigned m2 = __vmaxs2(A[u][2], pr.z);
            unsigned m3 = __vmaxs2(A[u][3], pr.w);
            const int co = co0 + cog * COT + u;
            float* op = out + (((size_t)b * COUT + co) * H + (h0 + r)) * W + j * 8;
            float f[8];
            f[0] = ((int)(m0 << 16) >> 16) * IQS;  f[1] = ((int)m0 >> 16) * IQS;
            f[2] = ((int)(m1 << 16) >> 16) * IQS;  f[3] = ((int)m1 >> 16) * IQS;
            f[4] = ((int)(m2 << 16) >> 16) * IQS;  f[5] = ((int)m2 >> 16) * IQS;
            f[6] = ((int)(m3 << 16) >> 16) * IQS;  f[7] = ((int)m3 >> 16) * IQS;
            *reinterpret_cast<float4*>(op)     = make_float4(f[0], f[1], f[2], f[3]);
            *reinterpret_cast<float4*>(op + 4) = make_float4(f[4], f[5], f[6], f[7]);
        }
    }
}

extern "C" void kernel_launch(void* const* d_in, const int* in_sizes, int n_in,
                              void* d_out, int out_size)
{
    const float* x   = (const float*)d_in[0];
    const float* wgt = (const float*)d_in[1];
    float* out       = (float*)d_out;

    prep_all<<<XQB + WQB, 256>>>(x, wgt);

    dim3 grid(1, H / TH, B * (COUT / COB));   // 1024 blocks
    maxconv2d_kernel<<<grid, 128>>>(out);
}

// round 13
// speedup vs baseline: 1.3012x; 1.0091x over previous
#include <cuda_runtime.h>
#include <cstdint>

#define QS    2048.0f
#define IQS   (1.0f/2048.0f)
#define NEGQ  (-20000)

// Problem constants
#define B    8
#define CIN  64
#define COUT 64
#define H    64
#define W    64
#define HW   (H*W)

// Padded quantized x: [B][CIN][66 rows][36 words] s16x2, two alignments
#define XPH  66
#define XPWW 36
#define XPC  (XPH*XPWW)   // 2376

// Dup weights: [CIN][COUT][12] words
#define WPC  12
#define WCIN (COUT*WPC)   // 768

// Tiling: block = 2 rows x 64 px x 16 co, 128 threads = 2 cin-half groups of 64
#define TH   2
#define COB  16
#define COT  4
#define NC   4
#define CHALF 32
#define XROWW 36
#define XS_C 288                    // 4 rows x 36 normal + 4 rows x 36 shifted
#define NXSW (NC*XS_C)              // 1152
#define WS_C (COB*WPC)              // 192
#define NWSW (NC*WS_C)              // 768
#define NITER (CHALF/NC)            // 8
#define REDS 20

__device__ __align__(16) unsigned xq_g [(size_t)B*CIN*XPC];   // normal: word k = cols(2k-1,2k)
__device__ __align__(16) unsigned xqs_g[(size_t)B*CIN*XPC];   // shifted: word k = cols(2k,2k+1)
__device__ __align__(16) unsigned wq_g [CIN*COUT*WPC];

#define CP_ASYNC16(dst, src) \
    asm volatile("cp.async.cg.shared.global [%0], [%1], 16;\n" :: "r"(dst), "l"(src))
#define CP_COMMIT() asm volatile("cp.async.commit_group;\n" ::: "memory")
#define CP_WAIT0()  asm volatile("cp.async.wait_group 0;\n" ::: "memory")

__device__ __forceinline__ unsigned pack16(int lo, int hi) {
    return (unsigned)(lo & 0xFFFF) | ((unsigned)hi << 16);
}

// ---- fused prep: x quads, both alignments (3x LDG.128) + weights ----
#define XQB 1188
#define WQB 192

__global__ void prep_all(const float* __restrict__ x, const float* __restrict__ wgt)
{
    if (blockIdx.x < XQB) {
        int q   = blockIdx.x * blockDim.x + threadIdx.x;
        int t   = q / 9;
        int sg  = q - t * 9;
        int hh  = t % XPH;
        int bc  = t / XPH;
        const bool rowok = (hh >= 1 && hh <= H);
        const float* row = x + (size_t)bc * HW + (hh - 1) * W;
        const bool aok = rowok && (sg >= 1);
        const bool mok = rowok && (sg < 8);
        float4 fa = aok ? *reinterpret_cast<const float4*>(row + sg * 8 - 4)
                        : make_float4(0.f, 0.f, 0.f, 0.f);
        float4 fm = mok ? *reinterpret_cast<const float4*>(row + sg * 8)
                        : make_float4(0.f, 0.f, 0.f, 0.f);
        float4 fh = mok ? *reinterpret_cast<const float4*>(row + sg * 8 + 4)
                        : make_float4(0.f, 0.f, 0.f, 0.f);
        // normal plane: word k = cols(2k-1, 2k); quad covers cols sg*8-1 .. sg*8+6
        int v[8];
        v[0] = aok ? __float2int_rn(fa.w * QS) : NEGQ;
        v[1] = mok ? __float2int_rn(fm.x * QS) : NEGQ;
        v[2] = mok ? __float2int_rn(fm.y * QS) : NEGQ;
        v[3] = mok ? __float2int_rn(fm.z * QS) : NEGQ;
        v[4] = mok ? __float2int_rn(fm.w * QS) : NEGQ;
        v[5] = mok ? __float2int_rn(fh.x * QS) : NEGQ;
        v[6] = mok ? __float2int_rn(fh.y * QS) : NEGQ;
        v[7] = mok ? __float2int_rn(fh.z * QS) : NEGQ;
        uint4 st;
        st.x = pack16(v[0], v[1]);
        st.y = pack16(v[2], v[3]);
        st.z = pack16(v[4], v[5]);
        st.w = pack16(v[6], v[7]);
        *reinterpret_cast<uint4*>(&xq_g[(size_t)q * 4]) = st;
        // shifted plane: word k = cols(2k, 2k+1); quad covers cols sg*8 .. sg*8+7
        int u0 = mok ? __float2int_rn(fm.x * QS) : NEGQ;
        int u1 = mok ? __float2int_rn(fm.y * QS) : NEGQ;
        int u2 = mok ? __float2int_rn(fm.z * QS) : NEGQ;
        int u3 = mok ? __float2int_rn(fm.w * QS) : NEGQ;
        int u4 = mok ? __float2int_rn(fh.x * QS) : NEGQ;
        int u5 = mok ? __float2int_rn(fh.y * QS) : NEGQ;
        int u6 = mok ? __float2int_rn(fh.z * QS) : NEGQ;
        int u7 = mok ? __float2int_rn(fh.w * QS) : NEGQ;
        uint4 ss;
        ss.x = pack16(u0, u1);
        ss.y = pack16(u2, u3);
        ss.z = pack16(u4, u5);
        ss.w = pack16(u6, u7);
        *reinterpret_cast<uint4*>(&xqs_g[(size_t)q * 4]) = ss;
    } else {
        int idx = (blockIdx.x - XQB) * blockDim.x + threadIdx.x;
        int tp  = idx % WPC;
        int qd  = idx / WPC;
        int co  = qd % COUT;
        int ci  = qd / COUT;
        int val = (tp < 9) ? __float2int_rn(wgt[(co * CIN + ci) * 9 + tp] * QS) : 0;
        wq_g[idx] = pack16(val, val);
    }
}

__device__ __forceinline__
void compute_chunk(const unsigned* __restrict__ xsb, const unsigned* __restrict__ wsb,
                   int c, int cog, int r, int j, unsigned (&A)[COT][4])
{
    unsigned tw[COT][9];
    const unsigned* wrow = wsb + c * WS_C + cog * (COT * WPC);
#pragma unroll
    for (int u = 0; u < COT; ++u) {
        uint4 q0 = *reinterpret_cast<const uint4*>(wrow + u * WPC);
        uint4 q1 = *reinterpret_cast<const uint4*>(wrow + u * WPC + 4);
        tw[u][0] = q0.x; tw[u][1] = q0.y; tw[u][2] = q0.z; tw[u][3] = q0.w;
        tw[u][4] = q1.x; tw[u][5] = q1.y; tw[u][6] = q1.z; tw[u][7] = q1.w;
        tw[u][8] = wrow[u * WPC + 8];
    }
#pragma unroll
    for (int dr = 0; dr < 3; ++dr) {
        const unsigned* basen = xsb + c * XS_C + (r + dr) * XROWW + 4 * j;
        uint4 q  = *reinterpret_cast<const uint4*>(basen);
        unsigned w4 = basen[4];
        uint4 sq = *reinterpret_cast<const uint4*>(basen + 4 * XROWW);  // shifted copy
        unsigned Wv[5] = { q.x, q.y, q.z, q.w, w4 };
        unsigned S[4]  = { sq.x, sq.y, sq.z, sq.w };
#pragma unroll
        for (int u = 0; u < COT; ++u) {
            const unsigned t0 = tw[u][dr * 3 + 0];
            const unsigned t1 = tw[u][dr * 3 + 1];
            const unsigned t2 = tw[u][dr * 3 + 2];
#pragma unroll
            for (int p = 0; p < 4; ++p) {
                A[u][p] = __viaddmax_s16x2(Wv[p],     t0, A[u][p]);
                A[u][p] = __viaddmax_s16x2(S[p],      t1, A[u][p]);
                A[u][p] = __viaddmax_s16x2(Wv[p + 1], t2, A[u][p]);
            }
        }
    }
}

__global__ __launch_bounds__(128, 7)
void maxconv2d_kernel(float* __restrict__ out)
{
    __shared__ __align__(16) unsigned xs[4 * NXSW];   // 18432 B ([half][buf])
    __shared__ __align__(16) unsigned ws[4 * NWSW];   // 12288 B

    const int tid  = threadIdx.x;
    const int half = tid >> 6;
    const int gt   = tid & 63;

    const int b   = blockIdx.z >> 2;
    const int co0 = (blockIdx.z & 3) * COB;
    const int h0  = blockIdx.y * TH;

    const int cog = gt >> 4;
    const int sp  = gt & 15;
    const int r   = sp >> 3;
    const int j   = sp & 7;

    const int s  = gt & 15;
    const int cl = gt >> 4;

    const unsigned NEG2 = pack16(NEGQ, NEGQ);
    unsigned A[COT][4];
#pragma unroll
    for (int u = 0; u < COT; ++u)
#pragma unroll
        for (int p = 0; p < 4; ++p) A[u][p] = NEG2;

    const size_t xoffg = (size_t)b * CIN * XPC + (size_t)half * CHALF * XPC + h0 * XPWW;
    const unsigned* xb  = xq_g  + xoffg;
    const unsigned* xbs = xqs_g + xoffg;
    const unsigned* wb  = wq_g + (size_t)half * CHALF * WCIN + co0 * WPC;

    const uint32_t xs_s = (uint32_t)__cvta_generic_to_shared(&xs[0]);
    const uint32_t ws_s = (uint32_t)__cvta_generic_to_shared(&ws[0]);

    // staging helper offsets: per cin, 144 normal words then 144 shifted words
#define STAGE_X(xd, xn, xsft)                                                        \
    {                                                                                \
        _Pragma("unroll")                                                            \
        for (int m = 0; m < 3; ++m)                                                  \
            if (m < 2 || s < 4) {                                                    \
                CP_ASYNC16((xd) + (uint32_t)(cl * XS_C + 4 * (s + 16 * m)) * 4u,     \
                           (xn) + cl * XPC + 4 * (s + 16 * m));                      \
                CP_ASYNC16((xd) + (uint32_t)(cl * XS_C + 144 + 4 * (s + 16 * m)) * 4u,\
                           (xsft) + cl * XPC + 4 * (s + 16 * m));                    \
            }                                                                        \
    }

    // ---- stage 0 into (half, buf=0) ----
    {
        const uint32_t xd = xs_s + (uint32_t)((half * 2) * NXSW) * 4u;
        const uint32_t wd = ws_s + (uint32_t)((half * 2) * NWSW) * 4u;
        STAGE_X(xd, xb, xbs)
#pragma unroll
        for (int m = 0; m < 3; ++m)
            CP_ASYNC16(wd + (uint32_t)(cl * WS_C + 4 * (s + 16 * m)) * 4u,
                       wb + cl * WCIN + 4 * (s + 16 * m));
        CP_COMMIT();
    }

    int buf = 0;
    for (int it = 0; it < NITER; ++it) {
        CP_WAIT0();
        __syncthreads();

        const bool more = (it + 1 < NITER);
        const unsigned* xc  = xb  + (it + 1) * NC * XPC;
        const unsigned* xcs = xbs + (it + 1) * NC * XPC;
        const unsigned* wc  = wb  + (it + 1) * NC * WCIN;
        const uint32_t xd = xs_s + (uint32_t)((half * 2 + (buf ^ 1)) * NXSW) * 4u;
        const uint32_t wd = ws_s + (uint32_t)((half * 2 + (buf ^ 1)) * NWSW) * 4u;

        const unsigned* xsb = xs + (half * 2 + buf) * NXSW;
        const unsigned* wsb = ws + (half * 2 + buf) * NWSW;

        compute_chunk(xsb, wsb, 0, cog, r, j, A);
        if (more) STAGE_X(xd, xc, xcs)
        compute_chunk(xsb, wsb, 1, cog, r, j, A);
        if (more) {
#pragma unroll
            for (int m = 0; m < 3; ++m)
                CP_ASYNC16(wd + (uint32_t)(cl * WS_C + 4 * (s + 16 * m)) * 4u,
                           wc + cl * WCIN + 4 * (s + 16 * m));
            CP_COMMIT();
        }
        compute_chunk(xsb, wsb, 2, cog, r, j, A);
        compute_chunk(xsb, wsb, 3, cog, r, j, A);

        buf ^= 1;
    }

    // ---- in-block combine (red aliased onto dead xs buffer) ----
    unsigned* red = xs;
    __syncthreads();   // all compute reads of xs done before overwrite
    if (half == 1) {
#pragma unroll
        for (int u = 0; u < COT; ++u) {
            uint4 st; st.x = A[u][0]; st.y = A[u][1]; st.z = A[u][2]; st.w = A[u][3];
            *reinterpret_cast<uint4*>(&red[gt * REDS + u * 4]) = st;
        }
    }
    __syncthreads();
    if (half == 0) {
#pragma unroll
        for (int u = 0; u < COT; ++u) {
            uint4 pr = *reinterpret_cast<const uint4*>(&red[gt * REDS + u * 4]);
            unsigned m0 = __vmaxs2(A[u][0], pr.x);
            unsigned m1 = __vmaxs2(A[u][1], pr.y);
            unsigned m2 = __vmaxs2(A[u][2], pr.z);
            unsigned m3 = __vmaxs2(A[u][3], pr.w);
            const int co = co0 + cog * COT + u;
            float* op = out + (((size_t)b * COUT + co) * H + (h0 + r)) * W + j * 8;
            float f[8];
            f[0] = ((int)(m0 << 16) >> 16) * IQS;  f[1] = ((int)m0 >> 16) * IQS;
            f[2] = ((int)(m1 << 16) >> 16) * IQS;  f[3] = ((int)m1 >> 16) * IQS;
            f[4] = ((int)(m2 << 16) >> 16) * IQS;  f[5] = ((int)m2 >> 16) * IQS;
            f[6] = ((int)(m3 << 16) >> 16) * IQS;  f[7] = ((int)m3 >> 16) * IQS;
            *reinterpret_cast<float4*>(op)     = make_float4(f[0], f[1], f[2], f[3]);
            *reinterpret_cast<float4*>(op + 4) = make_float4(f[4], f[5], f[6], f[7]);
        }
    }
#undef STAGE_X
}

extern "C" void kernel_launch(void* const* d_in, const int* in_sizes, int n_in,
                              void* d_out, int out_size)
{
    const float* x   = (const float*)d_in[0];
    const float* wgt = (const float*)d_in[1];
    float* out       = (float*)d_out;

    prep_all<<<XQB + WQB, 256>>>(x, wgt);

    dim3 grid(1, H / TH, B * (COUT / COB));   // 1024 blocks
    maxconv2d_kernel<<<grid, 128>>>(out);
}